// round 10
// baseline (speedup 1.0000x reference)
#include <cuda_runtime.h>
#include <cuda_fp16.h>
#include <cstdint>
#include <math.h>

// LSTM cell B=4096, I=1024, H=1024 — single-pass fp16 HMMA (mma.sync), fp32 accum.
// R10 = R9 winner + (a) per-CTA k-phase offset so co-resident CTAs' load/MMA phases
// decorrelate, (b) conv A/W paths interleaved by block parity.
// Core: 128x128 CTA tile, 256 thr / 8 warps, 2 CTAs/SM, warp tile 64x32,
// BK=64, 3-stage cp.async, gate-interleaved N (n = jj*4 + g).

#define MDIM 4096
#define HDIM 1024
#define KD   2048
#define BM   128
#define BN   128
#define TNJ  32
#define BK   64
#define NCHUNK 32                   // 2048 / 64
#define STAGES 3
#define STAGE_BYTES 32768           // A 128x128B + B 128x128B
#define STAGE_B_OFF 16384
#define SMEM_TOTAL (STAGES * STAGE_BYTES)   // 98304

// fp16 scratch (32 MB), device globals (sanctioned scratch workaround)
__device__ __align__(16) __half g_Ah[(size_t)MDIM * KD];
__device__ __align__(16) __half g_Wh[(size_t)4096 * KD];   // transposed [n][k]

__device__ __forceinline__ uint32_t smem_u32(const void* p) {
    uint32_t a;
    asm("{ .reg .u64 t; cvta.to.shared.u64 t, %1; cvt.u32.u64 %0, t; }" : "=r"(a) : "l"(p));
    return a;
}
__device__ __forceinline__ void cp_async16(uint32_t dst, const void* src) {
    asm volatile("cp.async.cg.shared.global [%0], [%1], 16;" :: "r"(dst), "l"(src));
}
#define CP_COMMIT() asm volatile("cp.async.commit_group;" ::: "memory")
#define CP_WAIT1()  asm volatile("cp.async.wait_group 1;" ::: "memory")

__device__ __forceinline__ void ldsm_x4(uint32_t r[4], uint32_t addr) {
    asm volatile("ldmatrix.sync.aligned.m8n8.x4.shared.b16 {%0,%1,%2,%3}, [%4];"
                 : "=r"(r[0]), "=r"(r[1]), "=r"(r[2]), "=r"(r[3]) : "r"(addr));
}
__device__ __forceinline__ void mma_fp16(float d[4], const uint32_t a[4],
                                         uint32_t b0, uint32_t b1) {
    asm volatile(
        "mma.sync.aligned.m16n8k16.row.col.f32.f16.f16.f32 "
        "{%0,%1,%2,%3}, {%4,%5,%6,%7}, {%8,%9}, {%0,%1,%2,%3};"
        : "+f"(d[0]), "+f"(d[1]), "+f"(d[2]), "+f"(d[3])
        : "r"(a[0]), "r"(a[1]), "r"(a[2]), "r"(a[3]), "r"(b0), "r"(b1));
}

__device__ __forceinline__ float fast_sigmoid(float x) {
    return 1.0f / (1.0f + __expf(-x));
}
__device__ __forceinline__ float fast_tanh(float x) {
    return 1.0f - 2.0f / (__expf(2.0f * x) + 1.0f);   // exact saturation at +-inf
}

// ---------------- merged conversion kernel (A/W interleaved by parity) ----------------
__global__ void conv_fused_kernel(const float* __restrict__ x,
                                  const float* __restrict__ h,
                                  const float* __restrict__ w_i,
                                  const float* __restrict__ w_h)
{
    if (!(blockIdx.x & 1)) {
        // A path: 8192 logical blocks
        size_t q = (size_t)(blockIdx.x >> 1) * 256 + threadIdx.x;
        int m = (int)(q >> 9);
        int k = ((int)q & 511) << 2;
        const float* src = (k < 1024) ? (x + (size_t)m * 1024 + k)
                                      : (h + (size_t)m * 1024 + (k - 1024));
        float4 v = *reinterpret_cast<const float4*>(src);
        size_t o = (size_t)m * KD + k;
        *reinterpret_cast<__half2*>(&g_Ah[o])     = __floats2half2_rn(v.x, v.y);
        *reinterpret_cast<__half2*>(&g_Ah[o + 2]) = __floats2half2_rn(v.z, v.w);
    } else {
        // W path: 8192 logical blocks (64 k-tiles x 128 n-tiles)
        __shared__ float tile[32][33];
        int bw = blockIdx.x >> 1;
        int tx = threadIdx.x & 31, ty = threadIdx.x >> 5;   // 32 x 8
        int k0 = (bw & 63) * 32, n0 = (bw >> 6) * 32;
        #pragma unroll
        for (int j = 0; j < 4; ++j) {
            int k = k0 + ty + j * 8;
            const float* src = (k < 1024) ? (w_i + (size_t)k * 4096)
                                          : (w_h + (size_t)(k - 1024) * 4096);
            tile[ty + j * 8][tx] = src[n0 + tx];
        }
        __syncthreads();
        #pragma unroll
        for (int j = 0; j < 4; ++j) {
            int n  = n0 + ty + j * 8;
            int kk = k0 + tx;
            g_Wh[(size_t)n * KD + kk] = __float2half_rn(tile[tx][ty + j * 8]);
        }
    }
}

// ---------------- main GEMM + LSTM kernel ----------------
__global__ __launch_bounds__(256, 2)
void lstm_hmma_kernel(const float* __restrict__ c_t,
                      const float* __restrict__ b_i,
                      const float* __restrict__ b_h,
                      float* __restrict__ out)
{
    extern __shared__ __align__(1024) char dsm[];
    const uint32_t sb = smem_u32(dsm);
    const int tid = threadIdx.x;
    const int wid = tid >> 5;
    const int lid = tid & 31;
    const int mbase = blockIdx.y * BM;
    const int nbase = blockIdx.x * TNJ;

    // k-phase offset: co-resident CTAs start at different chunks so their
    // load/LDSM windows overlap the partner's MMA bursts.
    const int coff = ((blockIdx.x + blockIdx.y * 5) & 3) * 8;

    const int wm = wid & 1;    // 2 row-groups of 64
    const int wn = wid >> 1;   // 4 col-groups of 32

    // ldmatrix per-thread stage-relative offsets (XOR with ks*32 per k-step)
    uint32_t pa[4], pb[2];
    #pragma unroll
    for (int i = 0; i < 4; ++i) {
        int row = wm * 64 + i * 16 + (lid & 15);
        int sub = ((lid >> 4) & 1) * 16;
        pa[i] = row * 128 + (sub ^ ((row & 7) << 4));
    }
    #pragma unroll
    for (int jh = 0; jh < 2; ++jh) {
        int row = wn * 32 + jh * 16 + ((lid >> 4) << 3) + (lid & 7);
        int sub = ((lid >> 3) & 1) * 16;
        pb[jh] = STAGE_B_OFF + row * 128 + (sub ^ ((row & 7) << 4));
    }

    float acc[4][4][4];
    #pragma unroll
    for (int i = 0; i < 4; ++i)
        #pragma unroll
        for (int j = 0; j < 4; ++j)
            #pragma unroll
            for (int c = 0; c < 4; ++c) acc[i][j][c] = 0.0f;

    auto load_stage = [&](int t) {
        const int koff = ((t + coff) & 31) * BK;
        const uint32_t abase = sb + (t % STAGES) * STAGE_BYTES;
        const uint32_t bbase = abase + STAGE_B_OFF;
        #pragma unroll
        for (int q = 0; q < 4; ++q) {            // A: 128 rows x 8 chunks / 256 thr
            int l = q * 256 + tid;
            int row = l >> 3, ck = l & 7;
            uint32_t boff = ck * 16;
            cp_async16(abase + row * 128 + (boff ^ ((row & 7) << 4)),
                       g_Ah + (size_t)(mbase + row) * KD + koff + ck * 8);
        }
        #pragma unroll
        for (int q = 0; q < 4; ++q) {            // B: 128 rows x 8 chunks / 256 thr
            int l = q * 256 + tid;
            int r = l >> 3, ck = l & 7;
            int n = ((r & 3) << 10) + nbase + (r >> 2);   // n = g*1024 + nbase + jj
            uint32_t boff = ck * 16;
            cp_async16(bbase + r * 128 + (boff ^ ((r & 7) << 4)),
                       g_Wh + (size_t)n * KD + koff + ck * 8);
        }
    };

    load_stage(0); CP_COMMIT();
    load_stage(1); CP_COMMIT();

    for (int t = 0; t < NCHUNK; ++t) {
        CP_WAIT1();
        __syncthreads();
        if (t + 2 < NCHUNK) load_stage(t + 2);
        CP_COMMIT();

        const uint32_t sbase = sb + (t % STAGES) * STAGE_BYTES;
        #pragma unroll
        for (int ks = 0; ks < 4; ++ks) {
            const uint32_t k0b = ks * 32;
            uint32_t a[4][4], b[2][4];
            #pragma unroll
            for (int i = 0; i < 4; ++i) ldsm_x4(a[i], sbase + (pa[i] ^ k0b));
            #pragma unroll
            for (int jh = 0; jh < 2; ++jh) ldsm_x4(b[jh], sbase + (pb[jh] ^ k0b));
            #pragma unroll
            for (int i = 0; i < 4; ++i) {
                mma_fp16(acc[i][0], a[i], b[0][0], b[0][1]);
                mma_fp16(acc[i][1], a[i], b[0][2], b[0][3]);
                mma_fp16(acc[i][2], a[i], b[1][0], b[1][1]);
                mma_fp16(acc[i][3], a[i], b[1][2], b[1][3]);
            }
        }
    }

    // ---- epilogue: hoist independent global loads BEFORE the staging barrier ----
    const int jj = tid & 31;
    const int rg = tid >> 5;            // 0..7, 16 rows each
    const int nb = nbase + jj;

    float bias_v[4];
    #pragma unroll
    for (int g = 0; g < 4; ++g)
        bias_v[g] = b_i[g * 1024 + nb] + b_h[g * 1024 + nb];

    float cold[16];
    #pragma unroll
    for (int rr = 0; rr < 16; ++rr)
        cold[rr] = c_t[(size_t)(mbase + rg * 16 + rr) * HDIM + nb];

    // stage ifgo tile to smem (reuse pipeline smem)
    __syncthreads();
    float* tile = reinterpret_cast<float*>(dsm);   // [128][132] floats
    const int trow0 = wm * 64 + (lid >> 2);
    const int tcol0 = wn * 32 + (lid & 3) * 2;
    #pragma unroll
    for (int i = 0; i < 4; ++i)
        #pragma unroll
        for (int j = 0; j < 4; ++j) {
            int r0 = trow0 + i * 16;
            int cc = tcol0 + j * 8;
            *reinterpret_cast<float2*>(&tile[r0 * 132 + cc]) =
                make_float2(acc[i][j][0], acc[i][j][1]);
            *reinterpret_cast<float2*>(&tile[(r0 + 8) * 132 + cc]) =
                make_float2(acc[i][j][2], acc[i][j][3]);
        }
    __syncthreads();

    float* out_h = out;
    float* out_c = out + (size_t)MDIM * HDIM;
    #pragma unroll
    for (int rr = 0; rr < 16; ++rr) {
        int row  = rg * 16 + rr;
        int grow = mbase + row;
        float4 v = *reinterpret_cast<const float4*>(&tile[row * 132 + jj * 4]);
        float iv = fast_sigmoid(v.x + bias_v[0]);
        float fv = fast_sigmoid(v.y + bias_v[1]);
        float gv = fast_tanh(v.z + bias_v[2]);
        float ov = fast_sigmoid(v.w + bias_v[3]);
        float c2 = fmaf(fv, cold[rr], iv * gv);
        out_c[(size_t)grow * HDIM + nb] = c2;
        out_h[(size_t)grow * HDIM + nb] = ov * fast_tanh(c2);
    }
}

extern "C" void kernel_launch(void* const* d_in, const int* in_sizes, int n_in,
                              void* d_out, int out_size)
{
    const float* x   = (const float*)d_in[0];
    const float* h_t = (const float*)d_in[1];
    const float* c_t = (const float*)d_in[2];
    const float* w_i = (const float*)d_in[3];
    const float* w_h = (const float*)d_in[4];
    const float* b_i = (const float*)d_in[5];
    const float* b_h = (const float*)d_in[6];
    float* out = (float*)d_out;

    static bool attr_set = false;
    if (!attr_set) {
        cudaFuncSetAttribute(lstm_hmma_kernel,
                             cudaFuncAttributeMaxDynamicSharedMemorySize, SMEM_TOTAL);
        attr_set = true;
    }

    conv_fused_kernel<<<16384, 256>>>(x, h_t, w_i, w_h);
    lstm_hmma_kernel<<<dim3(HDIM / TNJ, MDIM / BM), 256, SMEM_TOTAL>>>(c_t, b_i, b_h, out);
}

// round 12
// speedup vs baseline: 1.0309x; 1.0309x over previous
#include <cuda_runtime.h>
#include <cuda_fp16.h>
#include <cstdint>
#include <math.h>

// LSTM cell B=4096, I=1024, H=1024 — single-pass fp16 HMMA (mma.sync), fp32 accum.
// R12 = R11 with the W-path OOB transpose-store bug fixed (the first store loop
// already covers all 64 k-rows; the duplicate second loop read tile[] rows >=64
// and overwrote neighboring k-regions — removed).
// GEMM core: 128x128 CTA tile, 256 thr / 8 warps, 2 CTAs/SM, warp tile 64x32,
// BK=64, 3-stage cp.async, gate-interleaved N (n = jj*4 + g).

#define MDIM 4096
#define HDIM 1024
#define KD   2048
#define BM   128
#define BN   128
#define TNJ  32
#define BK   64
#define NCHUNK 32                   // 2048 / 64
#define STAGES 3
#define STAGE_BYTES 32768           // A 128x128B + B 128x128B
#define STAGE_B_OFF 16384
#define SMEM_TOTAL (STAGES * STAGE_BYTES)   // 98304

// fp16 scratch (32 MB), device globals (sanctioned scratch workaround)
__device__ __align__(16) __half g_Ah[(size_t)MDIM * KD];
__device__ __align__(16) __half g_Wh[(size_t)4096 * KD];   // transposed [n][k]

__device__ __forceinline__ uint32_t smem_u32(const void* p) {
    uint32_t a;
    asm("{ .reg .u64 t; cvta.to.shared.u64 t, %1; cvt.u32.u64 %0, t; }" : "=r"(a) : "l"(p));
    return a;
}
__device__ __forceinline__ void cp_async16(uint32_t dst, const void* src) {
    asm volatile("cp.async.cg.shared.global [%0], [%1], 16;" :: "r"(dst), "l"(src));
}
#define CP_COMMIT() asm volatile("cp.async.commit_group;" ::: "memory")
#define CP_WAIT1()  asm volatile("cp.async.wait_group 1;" ::: "memory")

__device__ __forceinline__ void ldsm_x4(uint32_t r[4], uint32_t addr) {
    asm volatile("ldmatrix.sync.aligned.m8n8.x4.shared.b16 {%0,%1,%2,%3}, [%4];"
                 : "=r"(r[0]), "=r"(r[1]), "=r"(r[2]), "=r"(r[3]) : "r"(addr));
}
__device__ __forceinline__ void mma_fp16(float d[4], const uint32_t a[4],
                                         uint32_t b0, uint32_t b1) {
    asm volatile(
        "mma.sync.aligned.m16n8k16.row.col.f32.f16.f16.f32 "
        "{%0,%1,%2,%3}, {%4,%5,%6,%7}, {%8,%9}, {%0,%1,%2,%3};"
        : "+f"(d[0]), "+f"(d[1]), "+f"(d[2]), "+f"(d[3])
        : "r"(a[0]), "r"(a[1]), "r"(a[2]), "r"(a[3]), "r"(b0), "r"(b1));
}

__device__ __forceinline__ float fast_sigmoid(float x) {
    return 1.0f / (1.0f + __expf(-x));
}
__device__ __forceinline__ float fast_tanh(float x) {
    return 1.0f - 2.0f / (__expf(2.0f * x) + 1.0f);   // exact saturation at +-inf
}

// ---------------- conversion kernel ----------------
// blocks [0, 2048): A path — thread handles 16 consecutive k (4 x LDG.128, MLP 4)
// blocks [2048, 6144): W path — 64(k) x 32(n) transpose tile, half2 stores
__global__ void conv_fused_kernel(const float* __restrict__ x,
                                  const float* __restrict__ h,
                                  const float* __restrict__ w_i,
                                  const float* __restrict__ w_h)
{
    if (blockIdx.x < 2048) {
        // 2048 blocks x 256 thr; each thread: 16 elems of a 2048-col row
        size_t q = (size_t)blockIdx.x * 256 + threadIdx.x;
        int m  = (int)(q >> 7);              // 128 threads per m-row
        int k0 = ((int)q & 127) << 4;        // 0..2032, within one source half
        const float* src = (k0 < 1024) ? (x + (size_t)m * 1024 + k0)
                                       : (h + (size_t)m * 1024 + (k0 - 1024));
        float4 v[4];
        #pragma unroll
        for (int i = 0; i < 4; ++i)
            v[i] = *reinterpret_cast<const float4*>(src + i * 4);
        size_t o = (size_t)m * KD + k0;
        #pragma unroll
        for (int i = 0; i < 4; ++i) {
            *reinterpret_cast<__half2*>(&g_Ah[o + i * 4])     = __floats2half2_rn(v[i].x, v[i].y);
            *reinterpret_cast<__half2*>(&g_Ah[o + i * 4 + 2]) = __floats2half2_rn(v[i].z, v[i].w);
        }
    } else {
        // 4096 blocks: 32 k-tiles (of 64) x 128 n-tiles (of 32)
        __shared__ float tile[64][33];
        int bw = blockIdx.x - 2048;
        int tx = threadIdx.x & 31, ty = threadIdx.x >> 5;   // 32 x 8
        int k0 = (bw & 31) * 64, n0 = (bw >> 5) * 32;
        #pragma unroll
        for (int j = 0; j < 8; ++j) {                       // 8 batched loads
            int k = k0 + ty + j * 8;
            const float* src = (k < 1024) ? (w_i + (size_t)k * 4096)
                                          : (w_h + (size_t)(k - 1024) * 4096);
            tile[ty + j * 8][tx] = src[n0 + tx];
        }
        __syncthreads();
        // transpose-store: for fixed n (ty, j), tx sweeps kk = k0 + 2*tx over all
        // 64 k-values (rows 0..63 of tile). 32 n x 32 pair-slots = full tile.
        #pragma unroll
        for (int j = 0; j < 4; ++j) {
            int n = n0 + ty + j * 8;
            __half2 hv = __floats2half2_rn(tile[2 * tx][ty + j * 8],
                                           tile[2 * tx + 1][ty + j * 8]);
            *reinterpret_cast<__half2*>(&g_Wh[(size_t)n * KD + k0 + 2 * tx]) = hv;
        }
    }
}

// ---------------- main GEMM + LSTM kernel ----------------
__global__ __launch_bounds__(256, 2)
void lstm_hmma_kernel(const float* __restrict__ c_t,
                      const float* __restrict__ b_i,
                      const float* __restrict__ b_h,
                      float* __restrict__ out)
{
    extern __shared__ __align__(1024) char dsm[];
    const uint32_t sb = smem_u32(dsm);
    const int tid = threadIdx.x;
    const int wid = tid >> 5;
    const int lid = tid & 31;
    const int mbase = blockIdx.y * BM;
    const int nbase = blockIdx.x * TNJ;

    const int wm = wid & 1;    // 2 row-groups of 64
    const int wn = wid >> 1;   // 4 col-groups of 32

    // ldmatrix per-thread stage-relative offsets (XOR with ks*32 per k-step)
    uint32_t pa[4], pb[2];
    #pragma unroll
    for (int i = 0; i < 4; ++i) {
        int row = wm * 64 + i * 16 + (lid & 15);
        int sub = ((lid >> 4) & 1) * 16;
        pa[i] = row * 128 + (sub ^ ((row & 7) << 4));
    }
    #pragma unroll
    for (int jh = 0; jh < 2; ++jh) {
        int row = wn * 32 + jh * 16 + ((lid >> 4) << 3) + (lid & 7);
        int sub = ((lid >> 3) & 1) * 16;
        pb[jh] = STAGE_B_OFF + row * 128 + (sub ^ ((row & 7) << 4));
    }

    float acc[4][4][4];
    #pragma unroll
    for (int i = 0; i < 4; ++i)
        #pragma unroll
        for (int j = 0; j < 4; ++j)
            #pragma unroll
            for (int c = 0; c < 4; ++c) acc[i][j][c] = 0.0f;

    auto load_stage = [&](int t) {
        const int koff = t * BK;
        const uint32_t abase = sb + (t % STAGES) * STAGE_BYTES;
        const uint32_t bbase = abase + STAGE_B_OFF;
        #pragma unroll
        for (int q = 0; q < 4; ++q) {            // A: 128 rows x 8 chunks / 256 thr
            int l = q * 256 + tid;
            int row = l >> 3, ck = l & 7;
            uint32_t boff = ck * 16;
            cp_async16(abase + row * 128 + (boff ^ ((row & 7) << 4)),
                       g_Ah + (size_t)(mbase + row) * KD + koff + ck * 8);
        }
        #pragma unroll
        for (int q = 0; q < 4; ++q) {            // B: 128 rows x 8 chunks / 256 thr
            int l = q * 256 + tid;
            int r = l >> 3, ck = l & 7;
            int n = ((r & 3) << 10) + nbase + (r >> 2);   // n = g*1024 + nbase + jj
            uint32_t boff = ck * 16;
            cp_async16(bbase + r * 128 + (boff ^ ((r & 7) << 4)),
                       g_Wh + (size_t)n * KD + koff + ck * 8);
        }
    };

    load_stage(0); CP_COMMIT();
    load_stage(1); CP_COMMIT();

    for (int t = 0; t < NCHUNK; ++t) {
        CP_WAIT1();
        __syncthreads();
        if (t + 2 < NCHUNK) load_stage(t + 2);
        CP_COMMIT();

        const uint32_t sbase = sb + (t % STAGES) * STAGE_BYTES;
        #pragma unroll
        for (int ks = 0; ks < 4; ++ks) {
            const uint32_t k0b = ks * 32;
            uint32_t a[4][4], b[2][4];
            #pragma unroll
            for (int jh = 0; jh < 2; ++jh) ldsm_x4(b[jh], sbase + (pb[jh] ^ k0b));
            #pragma unroll
            for (int i = 0; i < 4; ++i) ldsm_x4(a[i], sbase + (pa[i] ^ k0b));
            #pragma unroll
            for (int i = 0; i < 4; ++i) {
                mma_fp16(acc[i][0], a[i], b[0][0], b[0][1]);
                mma_fp16(acc[i][1], a[i], b[0][2], b[0][3]);
                mma_fp16(acc[i][2], a[i], b[1][0], b[1][1]);
                mma_fp16(acc[i][3], a[i], b[1][2], b[1][3]);
            }
        }
    }

    // ---- epilogue: hoist independent global loads BEFORE the staging barrier ----
    const int jj = tid & 31;
    const int rg = tid >> 5;            // 0..7, 16 rows each
    const int nb = nbase + jj;

    float bias_v[4];
    #pragma unroll
    for (int g = 0; g < 4; ++g)
        bias_v[g] = b_i[g * 1024 + nb] + b_h[g * 1024 + nb];

    float cold[16];
    #pragma unroll
    for (int rr = 0; rr < 16; ++rr)
        cold[rr] = c_t[(size_t)(mbase + rg * 16 + rr) * HDIM + nb];

    // stage ifgo tile to smem (reuse pipeline smem)
    __syncthreads();
    float* tile = reinterpret_cast<float*>(dsm);   // [128][132] floats
    const int trow0 = wm * 64 + (lid >> 2);
    const int tcol0 = wn * 32 + (lid & 3) * 2;
    #pragma unroll
    for (int i = 0; i < 4; ++i)
        #pragma unroll
        for (int j = 0; j < 4; ++j) {
            int r0 = trow0 + i * 16;
            int cc = tcol0 + j * 8;
            *reinterpret_cast<float2*>(&tile[r0 * 132 + cc]) =
                make_float2(acc[i][j][0], acc[i][j][1]);
            *reinterpret_cast<float2*>(&tile[(r0 + 8) * 132 + cc]) =
                make_float2(acc[i][j][2], acc[i][j][3]);
        }
    __syncthreads();

    float* out_h = out;
    float* out_c = out + (size_t)MDIM * HDIM;
    #pragma unroll
    for (int rr = 0; rr < 16; ++rr) {
        int row  = rg * 16 + rr;
        int grow = mbase + row;
        float4 v = *reinterpret_cast<const float4*>(&tile[row * 132 + jj * 4]);
        float iv = fast_sigmoid(v.x + bias_v[0]);
        float fv = fast_sigmoid(v.y + bias_v[1]);
        float gv = fast_tanh(v.z + bias_v[2]);
        float ov = fast_sigmoid(v.w + bias_v[3]);
        float c2 = fmaf(fv, cold[rr], iv * gv);
        out_c[(size_t)grow * HDIM + nb] = c2;
        out_h[(size_t)grow * HDIM + nb] = ov * fast_tanh(c2);
    }
}

extern "C" void kernel_launch(void* const* d_in, const int* in_sizes, int n_in,
                              void* d_out, int out_size)
{
    const float* x   = (const float*)d_in[0];
    const float* h_t = (const float*)d_in[1];
    const float* c_t = (const float*)d_in[2];
    const float* w_i = (const float*)d_in[3];
    const float* w_h = (const float*)d_in[4];
    const float* b_i = (const float*)d_in[5];
    const float* b_h = (const float*)d_in[6];
    float* out = (float*)d_out;

    static bool attr_set = false;
    if (!attr_set) {
        cudaFuncSetAttribute(lstm_hmma_kernel,
                             cudaFuncAttributeMaxDynamicSharedMemorySize, SMEM_TOTAL);
        attr_set = true;
    }

    conv_fused_kernel<<<6144, 256>>>(x, h_t, w_i, w_h);
    lstm_hmma_kernel<<<dim3(HDIM / TNJ, MDIM / BM), 256, SMEM_TOTAL>>>(c_t, b_i, b_h, out);
}